// round 3
// baseline (speedup 1.0000x reference)
#include <cuda_runtime.h>
#include <cuda_bf16.h>

// CrossHeadOnlineHadamardHook: 32-point Walsh-Hadamard across heads.
// x: (T, 4096) fp32 rows, T = 16384. heads = 32, HEAD_DIM = 128.
// For each (t, d): v[h] = x[t*4096 + h*128 + d], v = H32 * v / sqrt(32),
// written back to the same positions.
//
// Layout: one thread handles one token and a pair of adjacent d values
// (float2). Lanes within a warp take consecutive d-pairs, so every
// LDG.64 / STG.64 is a fully coalesced 256B warp transaction.
// The 32-point FWHT runs entirely in registers (5 stages, compile-time
// unrolled; the butterfly stage order is irrelevant for natural-order H).

#define NUM_HEADS 32
#define HEAD_DIM  128
#define HIDDEN    (NUM_HEADS * HEAD_DIM)      // 4096
#define PAIRS_PER_ROW (HIDDEN / 2)            // 2048 float2 per token row
#define DPAIRS_PER_TOKEN (HEAD_DIM / 2)       // 64 threads per token
#define HPAIR_STRIDE (HEAD_DIM / 2)           // 64 float2 between heads

__global__ __launch_bounds__(256)
void had32_crosshead_kernel(const float* __restrict__ x,
                            float* __restrict__ out,
                            int n_threads_total)
{
    int tid = blockIdx.x * 256 + threadIdx.x;
    if (tid >= n_threads_total) return;

    int t  = tid >> 6;          // token index (64 d-pairs per token)
    int dp = tid & 63;          // which float2 within the head dim

    size_t base = (size_t)t * PAIRS_PER_ROW + dp;
    const float2* __restrict__ px = reinterpret_cast<const float2*>(x) + base;
    float2*       __restrict__ py = reinterpret_cast<float2*>(out) + base;

    float2 v[NUM_HEADS];

    // 32 coalesced LDG.64: stride between heads = 128 floats = 64 float2
#pragma unroll
    for (int h = 0; h < NUM_HEADS; ++h) {
        v[h] = __ldg(px + (size_t)h * HPAIR_STRIDE);
    }

    // In-register 32-point FWHT (natural order)
#pragma unroll
    for (int s = 1; s < NUM_HEADS; s <<= 1) {
#pragma unroll
        for (int i = 0; i < NUM_HEADS; ++i) {
            if ((i & s) == 0) {
                float2 a = v[i];
                float2 b = v[i + s];
                v[i].x     = a.x + b.x;
                v[i].y     = a.y + b.y;
                v[i + s].x = a.x - b.x;
                v[i + s].y = a.y - b.y;
            }
        }
    }

    const float scl = 0.17677669529663687f;   // 1/sqrt(32)

    // 32 coalesced STG.64
#pragma unroll
    for (int h = 0; h < NUM_HEADS; ++h) {
        float2 r;
        r.x = v[h].x * scl;
        r.y = v[h].y * scl;
        py[(size_t)h * HPAIR_STRIDE] = r;
    }
}

extern "C" void kernel_launch(void* const* d_in, const int* in_sizes, int n_in,
                              void* d_out, int out_size)
{
    const float* x = (const float*)d_in[0];
    float* out = (float*)d_out;

    int n = in_sizes[0];                 // total fp32 elements (4*4096*4096)
    int n_threads = n >> 6;              // each thread handles 64 elements
    int blocks = (n_threads + 255) / 256;

    had32_crosshead_kernel<<<blocks, 256>>>(x, out, n_threads);
}